// round 7
// baseline (speedup 1.0000x reference)
#include <cuda_runtime.h>
#include <cuda_fp16.h>
#include <math.h>
#include <stdint.h>

// ---------------------------------------------------------------------------
// Problem constants
// ---------------------------------------------------------------------------
#define S_LEN 256
#define B_SZ  32
#define E_DIM 300
#define H_DIM 2400
#define N3H   (3 * H_DIM)            // 7200
#define M_ROWS (S_LEN * B_SZ)        // 8192

#define K1PAD 320                    // 300 -> mult of 32
#define K2PAD 2432                   // 2400 -> mult of 32
#define NPAD  7424                   // 7200 -> mult of 256

#define BM 128
#define BN 256
#define BK 32
#define NSTAGE 4
#define NGRP (NPAD / BN)             // 29

// SMEM planes, padded row stride 80 B (conflict-free ldmatrix)
#define ROWB 80
#define A_PLANE (128 * ROWB)         // 10240
#define B_PLANE (256 * ROWB)         // 20480
#define OFF_A   0
#define OFF_B   A_PLANE
#define STAGE_BYTES (A_PLANE + B_PLANE)          // 30720
#define GEMM_SMEM_BYTES (NSTAGE * STAGE_BYTES)   // 122880 (1 CTA/SM)

// ---------------------------------------------------------------------------
// Scratch (__device__ globals: allocation-free; zero-initialized at load,
// so padded K/N regions read as 0)
// ---------------------------------------------------------------------------
__device__ __align__(16) __half g_A1[(size_t)M_ROWS * K1PAD];
__device__ __align__(16) __half g_Ax[(size_t)M_ROWS * K2PAD];
__device__ __align__(16) __half g_W1[(size_t)NPAD * K1PAD];
__device__ __align__(16) __half g_W2[(size_t)NPAD * K2PAD];
__device__ __align__(16) __half g_W3[(size_t)NPAD * K2PAD];
__device__ __align__(16) __half g_gates[(size_t)M_ROWS * N3H];   // fp16 gates
__device__ float g_acc[B_SZ * H_DIM];

// ---------------------------------------------------------------------------
__device__ __forceinline__ uint32_t smem_u32(const void* p) {
    uint32_t a;
    asm("{ .reg .u64 t; cvta.to.shared.u64 t, %1; cvt.u32.u64 %0, t; }" : "=r"(a) : "l"(p));
    return a;
}
__device__ __forceinline__ float sigmoid_f(float x) {
    return __fdividef(1.0f, 1.0f + __expf(-x));
}
__device__ __forceinline__ float tanh_fast(float x) {
    return 1.0f - __fdividef(2.0f, __expf(2.0f * x) + 1.0f);
}

#define CP_ASYNC16(dst, src) \
    asm volatile("cp.async.cg.shared.global [%0], [%1], 16;" :: "r"(dst), "l"(src) : "memory")
#define CP_COMMIT() asm volatile("cp.async.commit_group;" ::: "memory")
#define CP_WAIT(n)  asm volatile("cp.async.wait_group %0;" :: "n"(n) : "memory")

#define LDSM_X4(r0, r1, r2, r3, addr) \
    asm volatile("ldmatrix.sync.aligned.m8n8.x4.shared.b16 {%0,%1,%2,%3}, [%4];" \
                 : "=r"(r0), "=r"(r1), "=r"(r2), "=r"(r3) : "r"(addr))

#define MMA_FP16(d, a, b0, b1) \
    asm volatile("mma.sync.aligned.m16n8k16.row.col.f32.f16.f16.f32 " \
                 "{%0,%1,%2,%3}, {%4,%5,%6,%7}, {%8,%9}, {%0,%1,%2,%3};" \
                 : "+f"((d)[0]), "+f"((d)[1]), "+f"((d)[2]), "+f"((d)[3]) \
                 : "r"((a)[0]), "r"((a)[1]), "r"((a)[2]), "r"((a)[3]), "r"(b0), "r"(b1))

// ---------------------------------------------------------------------------
// fp32 -> fp16 conversions, vectorized
// ---------------------------------------------------------------------------
__global__ void cvt_W_kernel(const float* __restrict__ in, int K4, int Kpad, int which) {
    __half* w = (which == 0) ? g_W1 : (which == 1) ? g_W2 : g_W3;
    const int r = blockIdx.x;
    const float4* row = (const float4*)(in + (size_t)r * (K4 * 4));
    for (int k4 = threadIdx.x; k4 < K4; k4 += blockDim.x) {
        const float4 x = row[k4];
        __half2 h01 = __floats2half2_rn(x.x, x.y);
        __half2 h23 = __floats2half2_rn(x.z, x.w);
        uint2 ph;
        ph.x = *(uint32_t*)&h01; ph.y = *(uint32_t*)&h23;
        *(uint2*)(w + (size_t)r * Kpad + k4 * 4) = ph;
    }
}

__global__ void cvt_A1_kernel(const float* __restrict__ sent) {
    const int r = blockIdx.x;
    const float4* row = (const float4*)(sent + (size_t)r * E_DIM);
    for (int k4 = threadIdx.x; k4 < E_DIM / 4; k4 += blockDim.x) {
        const float4 x = row[k4];
        __half2 h01 = __floats2half2_rn(x.x, x.y);
        __half2 h23 = __floats2half2_rn(x.z, x.w);
        uint2 ph;
        ph.x = *(uint32_t*)&h01; ph.y = *(uint32_t*)&h23;
        *(uint2*)(g_A1 + (size_t)r * K1PAD + k4 * 4) = ph;
    }
}

// ---------------------------------------------------------------------------
// fp16 HMMA GEMM (fp32 accum): g_gates[m,n] = act( A[m,:].W[n,:] + bias[n] )
// BM=128, BN=256, warp tile 64x64 (8 warps, 2x4), 4-stage pipeline, 1 CTA/SM.
// ---------------------------------------------------------------------------
__global__ __launch_bounds__(256, 1) void gemm_tc(int layer, const float* __restrict__ bias) {
    const __half *A, *W;
    int Kpad;
    if (layer == 1)      { A = g_A1; W = g_W1; Kpad = K1PAD; }
    else if (layer == 2) { A = g_Ax; W = g_W2; Kpad = K2PAD; }
    else                 { A = g_Ax; W = g_W3; Kpad = K2PAD; }
    const int NT = Kpad / BK;

    // m-strip swizzle for L2 reuse: strips of 8 m-groups, n fastest
    const int bx = blockIdx.x;
    const int strip = bx / (8 * NGRP);
    const int rem   = bx % (8 * NGRP);
    const int mg    = strip * 8 + (rem % 8);
    const int ng    = rem / 8;
    const int m0 = mg * BM;
    const int n0 = ng * BN;

    extern __shared__ char smem_raw[];
    const uint32_t sbase = smem_u32(smem_raw);

    const int tid = threadIdx.x;
    const int wid = tid >> 5;
    const int lid = tid & 31;
    const int wm = (wid & 1) * 64;       // warp m offset (0/64)
    const int wn = (wid >> 1) * 64;      // warp n offset (0/64/128/192)

    auto load_chunk = [&](int t, int slot) {
        const uint32_t st = sbase + (uint32_t)slot * STAGE_BYTES;
        const int kc = t * BK;
        // A: 128 rows x 4 16B-units = 512 lane-ops
#pragma unroll
        for (int i = 0; i < 2; i++) {
            const int u = tid + i * 256;
            const int r = u >> 2, c = u & 3;
            const uint32_t so = (uint32_t)(r * ROWB + c * 16);
            CP_ASYNC16(st + OFF_A + so, A + (size_t)(m0 + r) * Kpad + kc + c * 8);
        }
        // B: 256 rows x 4 units = 1024 lane-ops
#pragma unroll
        for (int i = 0; i < 4; i++) {
            const int u = tid + i * 256;
            const int r = u >> 2, c = u & 3;
            const uint32_t so = (uint32_t)(r * ROWB + c * 16);
            CP_ASYNC16(st + OFF_B + so, W + (size_t)(n0 + r) * Kpad + kc + c * 8);
        }
        CP_COMMIT();
    };

    float d[4][8][4];
#pragma unroll
    for (int mi = 0; mi < 4; mi++)
#pragma unroll
        for (int ni = 0; ni < 8; ni++)
#pragma unroll
            for (int q = 0; q < 4; q++) d[mi][ni][q] = 0.0f;

    const uint32_t a_row = (uint32_t)(wm + (lid & 15));
    const uint32_t a_kb  = (uint32_t)((lid >> 4) * 16);
    const uint32_t b_row = (uint32_t)(wn + (lid & 7) + ((lid >> 4) & 1) * 8);
    const uint32_t b_kb  = (uint32_t)(((lid >> 3) & 1) * 16);

    // Prologue: fill 3 of 4 stages
    load_chunk(0, 0);
    load_chunk(1, 1);
    load_chunk(2, 2);

    for (int t = 0; t < NT; ++t) {
        CP_WAIT(2);
        __syncthreads();

        if (t + 3 < NT) load_chunk(t + 3, (t + 3) % NSTAGE);
        else CP_COMMIT();

        const uint32_t st = sbase + (uint32_t)(t % NSTAGE) * STAGE_BYTES;
#pragma unroll
        for (int ks = 0; ks < 2; ks++) {
            const uint32_t kbyte = (uint32_t)(ks * 32);
            uint32_t af[4][4];
#pragma unroll
            for (int mi = 0; mi < 4; mi++) {
                const uint32_t ra = st + OFF_A + (a_row + mi * 16) * ROWB + kbyte + a_kb;
                LDSM_X4(af[mi][0], af[mi][1], af[mi][2], af[mi][3], ra);
            }
            uint32_t bf[8][2];
#pragma unroll
            for (int j = 0; j < 4; j++) {
                const uint32_t rb = st + OFF_B + (b_row + j * 16) * ROWB + kbyte + b_kb;
                LDSM_X4(bf[2*j][0], bf[2*j][1], bf[2*j+1][0], bf[2*j+1][1], rb);
            }
#pragma unroll
            for (int mi = 0; mi < 4; mi++)
#pragma unroll
                for (int ni = 0; ni < 8; ni++)
                    MMA_FP16(d[mi][ni], af[mi], bf[ni][0], bf[ni][1]);
        }
    }

    __syncthreads();

    // Epilogue: bias + activation + fp16 store
    const int er = lid >> 2;
    const int ec = (lid & 3) * 2;
#pragma unroll
    for (int mi = 0; mi < 4; mi++) {
#pragma unroll
        for (int ni = 0; ni < 8; ni++) {
            const int n = n0 + wn + ni * 8 + ec;     // even; H_DIM even -> no straddle
            if (n >= N3H) continue;
            const int m = m0 + wm + mi * 16 + er;
            const float2 bs = *(const float2*)(bias + n);
            const bool tA = (n < H_DIM);
            {
                const float y0 = d[mi][ni][0] + bs.x;
                const float y1 = d[mi][ni][1] + bs.y;
                const float v0 = tA ? tanh_fast(y0) : sigmoid_f(y0);
                const float v1 = tA ? tanh_fast(y1) : sigmoid_f(y1);
                *(__half2*)(g_gates + (size_t)m * N3H + n) = __floats2half2_rn(v0, v1);
            }
            {
                const float y0 = d[mi][ni][2] + bs.x;
                const float y1 = d[mi][ni][3] + bs.y;
                const float v0 = tA ? tanh_fast(y0) : sigmoid_f(y0);
                const float v1 = tA ? tanh_fast(y1) : sigmoid_f(y1);
                *(__half2*)(g_gates + (size_t)(m + 8) * N3H + n) = __floats2half2_rn(v0, v1);
            }
        }
    }
}

// ---------------------------------------------------------------------------
// fo-pool scan: 4 h-lanes/thread, fp16 gate reads, fp32 recurrence.
// ---------------------------------------------------------------------------
__device__ __forceinline__ float4 ld_gates4(const __half* p) {
    const uint2 u = *(const uint2*)p;
    const float2 a = __half22float2(*(const __half2*)&u.x);
    const float2 b = __half22float2(*(const __half2*)&u.y);
    return make_float4(a.x, a.y, b.x, b.y);
}

__global__ void scan_kernel(int mode, const int* __restrict__ sent_len,
                            float* __restrict__ out)
{
    const int tix = blockIdx.x * blockDim.x + threadIdx.x;
    if (tix >= (B_SZ * H_DIM) / 4) return;
    const int flat = tix * 4;
    const int b = flat / H_DIM;
    const int h = flat - b * H_DIM;

    const size_t stride = (size_t)B_SZ * N3H;
    size_t base = (size_t)b * N3H + h;

    float4 c = make_float4(0.f, 0.f, 0.f, 0.f);

    if (mode != 2) {
        size_t xbase = (size_t)b * K2PAD + h;
        const size_t xstride = (size_t)B_SZ * K2PAD;
#pragma unroll 4
        for (int s = 0; s < S_LEN; ++s) {
            const float4 z = ld_gates4(g_gates + base);
            const float4 f = ld_gates4(g_gates + base + H_DIM);
            const float4 o = ld_gates4(g_gates + base + 2 * H_DIM);
            c.x = fmaf(f.x, c.x - z.x, z.x);
            c.y = fmaf(f.y, c.y - z.y, z.y);
            c.z = fmaf(f.z, c.z - z.z, z.z);
            c.w = fmaf(f.w, c.w - z.w, z.w);
            __half2 h01 = __floats2half2_rn(o.x * c.x, o.y * c.y);
            __half2 h23 = __floats2half2_rn(o.z * c.z, o.w * c.w);
            uint2 pk;
            pk.x = *(uint32_t*)&h01;
            pk.y = *(uint32_t*)&h23;
            *(uint2*)(g_Ax + xbase) = pk;
            base  += stride;
            xbase += xstride;
        }
    } else {
#pragma unroll 4
        for (int s = 0; s < S_LEN; ++s) {
            const float4 z = ld_gates4(g_gates + base);
            const float4 f = ld_gates4(g_gates + base + H_DIM);
            c.x = fmaf(f.x, c.x - z.x, z.x);
            c.y = fmaf(f.y, c.y - z.y, z.y);
            c.z = fmaf(f.z, c.z - z.z, z.z);
            c.w = fmaf(f.w, c.w - z.w, z.w);
            base += stride;
        }
    }

    if (mode == 0) {
        *(float4*)(g_acc + flat) = c;
    } else if (mode == 1) {
        float4 a = *(const float4*)(g_acc + flat);
        a.x += c.x; a.y += c.y; a.z += c.z; a.w += c.w;
        *(float4*)(g_acc + flat) = a;
    } else {
        const float inv = 1.0f / (float)sent_len[b];
        float4 a = *(const float4*)(g_acc + flat);
        float4 v;
        v.x = (a.x + c.x) * inv;
        v.y = (a.y + c.y) * inv;
        v.z = (a.z + c.z) * inv;
        v.w = (a.w + c.w) * inv;
        *(float4*)(out + flat) = v;
    }
}

// ---------------------------------------------------------------------------
extern "C" void kernel_launch(void* const* d_in, const int* in_sizes, int n_in,
                              void* d_out, int out_size)
{
    const float* sent     = (const float*)d_in[0];
    const int*   sent_len = (const int*)  d_in[1];
    const float* W1 = (const float*)d_in[2];
    const float* b1 = (const float*)d_in[3];
    const float* W2 = (const float*)d_in[4];
    const float* b2 = (const float*)d_in[5];
    const float* W3 = (const float*)d_in[6];
    const float* b3 = (const float*)d_in[7];
    float* out = (float*)d_out;

    cudaFuncSetAttribute(gemm_tc, cudaFuncAttributeMaxDynamicSharedMemorySize, GEMM_SMEM_BYTES);

    cvt_W_kernel<<<N3H, 128>>>(W1, E_DIM / 4, K1PAD, 0);
    cvt_W_kernel<<<N3H, 128>>>(W2, H_DIM / 4, K2PAD, 1);
    cvt_W_kernel<<<N3H, 128>>>(W3, H_DIM / 4, K2PAD, 2);
    cvt_A1_kernel<<<M_ROWS, 64>>>(sent);

    const int nblocks = (M_ROWS / BM) * NGRP;             // 64 * 29 = 1856
    const int sblocks = ((B_SZ * H_DIM) / 4 + 127) / 128; // 150

    gemm_tc<<<nblocks, 256, GEMM_SMEM_BYTES>>>(1, b1);
    scan_kernel<<<sblocks, 128>>>(0, sent_len, out);

    gemm_tc<<<nblocks, 256, GEMM_SMEM_BYTES>>>(2, b2);
    scan_kernel<<<sblocks, 128>>>(1, sent_len, out);

    gemm_tc<<<nblocks, 256, GEMM_SMEM_BYTES>>>(3, b3);
    scan_kernel<<<sblocks, 128>>>(2, sent_len, out);
}

// round 8
// speedup vs baseline: 1.3235x; 1.3235x over previous
#include <cuda_runtime.h>
#include <cuda_fp16.h>
#include <math.h>
#include <stdint.h>

// ---------------------------------------------------------------------------
// Problem constants
// ---------------------------------------------------------------------------
#define S_LEN 256
#define B_SZ  32
#define E_DIM 300
#define H_DIM 2400
#define N3H   (3 * H_DIM)            // 7200
#define M_ROWS (S_LEN * B_SZ)        // 8192

#define K1PAD 320                    // 300 -> mult of 64
#define K2PAD 2432                   // 2400 -> mult of 64
#define NPAD  7296                   // 7200 -> mult of 128

#define BM 128
#define BN 128
#define BK 64
#define NSTAGE 3
#define NGRP (NPAD / BN)             // 57

// SMEM plane: 128 rows x 64 fp16 (128 B) padded to 144 B (conflict-free ldmatrix)
#define ROWB 144
#define PLANE_BYTES (128 * ROWB)     // 18432
#define OFF_A   0
#define OFF_B   PLANE_BYTES
#define STAGE_BYTES (2 * PLANE_BYTES)            // 36864
#define GEMM_SMEM_BYTES (NSTAGE * STAGE_BYTES)   // 110592 (x2 CTA = 221184 <= 228K)

// ---------------------------------------------------------------------------
// Scratch (__device__ globals: allocation-free; zero-initialized at load,
// so padded K/N regions read as 0)
// ---------------------------------------------------------------------------
__device__ __align__(16) __half g_A1[(size_t)M_ROWS * K1PAD];
__device__ __align__(16) __half g_Ax[(size_t)M_ROWS * K2PAD];
__device__ __align__(16) __half g_W1[(size_t)NPAD * K1PAD];
__device__ __align__(16) __half g_W2[(size_t)NPAD * K2PAD];
__device__ __align__(16) __half g_W3[(size_t)NPAD * K2PAD];
__device__ __align__(16) __half g_gates[(size_t)M_ROWS * N3H];   // fp16 gates
__device__ float g_acc[B_SZ * H_DIM];

// ---------------------------------------------------------------------------
__device__ __forceinline__ uint32_t smem_u32(const void* p) {
    uint32_t a;
    asm("{ .reg .u64 t; cvta.to.shared.u64 t, %1; cvt.u32.u64 %0, t; }" : "=r"(a) : "l"(p));
    return a;
}
__device__ __forceinline__ float sigmoid_f(float x) {
    return __fdividef(1.0f, 1.0f + __expf(-x));
}
__device__ __forceinline__ float tanh_fast(float x) {
    return 1.0f - __fdividef(2.0f, __expf(2.0f * x) + 1.0f);
}

#define CP_ASYNC16(dst, src) \
    asm volatile("cp.async.cg.shared.global [%0], [%1], 16;" :: "r"(dst), "l"(src) : "memory")
#define CP_COMMIT() asm volatile("cp.async.commit_group;" ::: "memory")
#define CP_WAIT(n)  asm volatile("cp.async.wait_group %0;" :: "n"(n) : "memory")

#define LDSM_X4(r0, r1, r2, r3, addr) \
    asm volatile("ldmatrix.sync.aligned.m8n8.x4.shared.b16 {%0,%1,%2,%3}, [%4];" \
                 : "=r"(r0), "=r"(r1), "=r"(r2), "=r"(r3) : "r"(addr))

#define MMA_FP16(d, a, b0, b1) \
    asm volatile("mma.sync.aligned.m16n8k16.row.col.f32.f16.f16.f32 " \
                 "{%0,%1,%2,%3}, {%4,%5,%6,%7}, {%8,%9}, {%0,%1,%2,%3};" \
                 : "+f"((d)[0]), "+f"((d)[1]), "+f"((d)[2]), "+f"((d)[3]) \
                 : "r"((a)[0]), "r"((a)[1]), "r"((a)[2]), "r"((a)[3]), "r"(b0), "r"(b1))

// ---------------------------------------------------------------------------
// fp32 -> fp16 conversions, vectorized
// ---------------------------------------------------------------------------
__global__ void cvt_W_kernel(const float* __restrict__ in, int K4, int Kpad, int which) {
    __half* w = (which == 0) ? g_W1 : (which == 1) ? g_W2 : g_W3;
    const int r = blockIdx.x;
    const float4* row = (const float4*)(in + (size_t)r * (K4 * 4));
    for (int k4 = threadIdx.x; k4 < K4; k4 += blockDim.x) {
        const float4 x = row[k4];
        __half2 h01 = __floats2half2_rn(x.x, x.y);
        __half2 h23 = __floats2half2_rn(x.z, x.w);
        uint2 ph;
        ph.x = *(uint32_t*)&h01; ph.y = *(uint32_t*)&h23;
        *(uint2*)(w + (size_t)r * Kpad + k4 * 4) = ph;
    }
}

__global__ void cvt_A1_kernel(const float* __restrict__ sent) {
    const int r = blockIdx.x;
    const float4* row = (const float4*)(sent + (size_t)r * E_DIM);
    for (int k4 = threadIdx.x; k4 < E_DIM / 4; k4 += blockDim.x) {
        const float4 x = row[k4];
        __half2 h01 = __floats2half2_rn(x.x, x.y);
        __half2 h23 = __floats2half2_rn(x.z, x.w);
        uint2 ph;
        ph.x = *(uint32_t*)&h01; ph.y = *(uint32_t*)&h23;
        *(uint2*)(g_A1 + (size_t)r * K1PAD + k4 * 4) = ph;
    }
}

// ---------------------------------------------------------------------------
// fp16 HMMA GEMM (fp32 accum): g_gates[m,n] = act( A[m,:].W[n,:] + bias[n] )
// BM=128, BN=128, BK=64, warp tile 64x32, 3-stage pipeline, 2 CTAs/SM.
// ---------------------------------------------------------------------------
__global__ __launch_bounds__(256, 2) void gemm_tc(int layer, const float* __restrict__ bias) {
    const __half *A, *W;
    int Kpad;
    if (layer == 1)      { A = g_A1; W = g_W1; Kpad = K1PAD; }
    else if (layer == 2) { A = g_Ax; W = g_W2; Kpad = K2PAD; }
    else                 { A = g_Ax; W = g_W3; Kpad = K2PAD; }
    const int NT = Kpad / BK;

    // m-strip swizzle for L2 reuse: strips of 8 m-groups, n fastest
    const int bx = blockIdx.x;
    const int strip = bx / (8 * NGRP);
    const int rem   = bx % (8 * NGRP);
    const int mg    = strip * 8 + (rem % 8);
    const int ng    = rem / 8;
    const int m0 = mg * BM;
    const int n0 = ng * BN;

    extern __shared__ char smem_raw[];
    const uint32_t sbase = smem_u32(smem_raw);

    const int tid = threadIdx.x;
    const int wid = tid >> 5;
    const int lid = tid & 31;
    const int wm = (wid & 1) * 64;
    const int wn = (wid >> 1) * 32;

    auto load_chunk = [&](int t, int slot) {
        const uint32_t st = sbase + (uint32_t)slot * STAGE_BYTES;
        const int kc = t * BK;
        // Each plane: 128 rows x 8 16B-units = 1024 lane-ops
#pragma unroll
        for (int i = 0; i < 4; i++) {
            const int u = tid + i * 256;
            const int r = u >> 3, c = u & 7;
            const uint32_t so = (uint32_t)(r * ROWB + c * 16);
            CP_ASYNC16(st + OFF_A + so, A + (size_t)(m0 + r) * Kpad + kc + c * 8);
            CP_ASYNC16(st + OFF_B + so, W + (size_t)(n0 + r) * Kpad + kc + c * 8);
        }
        CP_COMMIT();
    };

    float d[4][4][4];
#pragma unroll
    for (int mi = 0; mi < 4; mi++)
#pragma unroll
        for (int ni = 0; ni < 4; ni++)
#pragma unroll
            for (int q = 0; q < 4; q++) d[mi][ni][q] = 0.0f;

    const uint32_t a_row = (uint32_t)(wm + (lid & 15));
    const uint32_t a_kb  = (uint32_t)((lid >> 4) * 16);
    const uint32_t b_row = (uint32_t)(wn + (lid & 7) + ((lid >> 4) & 1) * 8);
    const uint32_t b_kb  = (uint32_t)(((lid >> 3) & 1) * 16);

    // Prologue: fill 2 of 3 stages
    load_chunk(0, 0);
    load_chunk(1, 1);

    for (int t = 0; t < NT; ++t) {
        CP_WAIT(1);            // chunk t landed (t+1 may still be in flight)
        __syncthreads();       // all warps done with slot being refilled

        if (t + 2 < NT) load_chunk(t + 2, (t + 2) % NSTAGE);
        else CP_COMMIT();      // keep outstanding-group count uniform

        const uint32_t st = sbase + (uint32_t)(t % NSTAGE) * STAGE_BYTES;
#pragma unroll
        for (int ks = 0; ks < 4; ks++) {
            const uint32_t kbyte = (uint32_t)(ks * 32);
            uint32_t af[4][4];
#pragma unroll
            for (int mi = 0; mi < 4; mi++) {
                const uint32_t ra = st + OFF_A + (a_row + mi * 16) * ROWB + kbyte + a_kb;
                LDSM_X4(af[mi][0], af[mi][1], af[mi][2], af[mi][3], ra);
            }
            uint32_t bf[4][2];
#pragma unroll
            for (int j = 0; j < 2; j++) {
                const uint32_t rb = st + OFF_B + (b_row + j * 16) * ROWB + kbyte + b_kb;
                LDSM_X4(bf[2*j][0], bf[2*j][1], bf[2*j+1][0], bf[2*j+1][1], rb);
            }
#pragma unroll
            for (int mi = 0; mi < 4; mi++)
#pragma unroll
                for (int ni = 0; ni < 4; ni++)
                    MMA_FP16(d[mi][ni], af[mi], bf[ni][0], bf[ni][1]);
        }
    }

    __syncthreads();

    // Epilogue: bias + activation + fp16 store
    const int er = lid >> 2;
    const int ec = (lid & 3) * 2;
#pragma unroll
    for (int mi = 0; mi < 4; mi++) {
#pragma unroll
        for (int ni = 0; ni < 4; ni++) {
            const int n = n0 + wn + ni * 8 + ec;     // even; H_DIM even -> no straddle
            if (n >= N3H) continue;
            const int m = m0 + wm + mi * 16 + er;
            const float2 bs = *(const float2*)(bias + n);
            const bool tA = (n < H_DIM);
            {
                const float y0 = d[mi][ni][0] + bs.x;
                const float y1 = d[mi][ni][1] + bs.y;
                const float v0 = tA ? tanh_fast(y0) : sigmoid_f(y0);
                const float v1 = tA ? tanh_fast(y1) : sigmoid_f(y1);
                *(__half2*)(g_gates + (size_t)m * N3H + n) = __floats2half2_rn(v0, v1);
            }
            {
                const float y0 = d[mi][ni][2] + bs.x;
                const float y1 = d[mi][ni][3] + bs.y;
                const float v0 = tA ? tanh_fast(y0) : sigmoid_f(y0);
                const float v1 = tA ? tanh_fast(y1) : sigmoid_f(y1);
                *(__half2*)(g_gates + (size_t)(m + 8) * N3H + n) = __floats2half2_rn(v0, v1);
            }
        }
    }
}

// ---------------------------------------------------------------------------
// fo-pool scan: 4 h-lanes/thread, fp16 gate reads, fp32 recurrence.
// ---------------------------------------------------------------------------
__device__ __forceinline__ float4 ld_gates4(const __half* p) {
    const uint2 u = *(const uint2*)p;
    const float2 a = __half22float2(*(const __half2*)&u.x);
    const float2 b = __half22float2(*(const __half2*)&u.y);
    return make_float4(a.x, a.y, b.x, b.y);
}

__global__ void scan_kernel(int mode, const int* __restrict__ sent_len,
                            float* __restrict__ out)
{
    const int tix = blockIdx.x * blockDim.x + threadIdx.x;
    if (tix >= (B_SZ * H_DIM) / 4) return;
    const int flat = tix * 4;
    const int b = flat / H_DIM;
    const int h = flat - b * H_DIM;

    const size_t stride = (size_t)B_SZ * N3H;
    size_t base = (size_t)b * N3H + h;

    float4 c = make_float4(0.f, 0.f, 0.f, 0.f);

    if (mode != 2) {
        size_t xbase = (size_t)b * K2PAD + h;
        const size_t xstride = (size_t)B_SZ * K2PAD;
#pragma unroll 4
        for (int s = 0; s < S_LEN; ++s) {
            const float4 z = ld_gates4(g_gates + base);
            const float4 f = ld_gates4(g_gates + base + H_DIM);
            const float4 o = ld_gates4(g_gates + base + 2 * H_DIM);
            c.x = fmaf(f.x, c.x - z.x, z.x);
            c.y = fmaf(f.y, c.y - z.y, z.y);
            c.z = fmaf(f.z, c.z - z.z, z.z);
            c.w = fmaf(f.w, c.w - z.w, z.w);
            __half2 h01 = __floats2half2_rn(o.x * c.x, o.y * c.y);
            __half2 h23 = __floats2half2_rn(o.z * c.z, o.w * c.w);
            uint2 pk;
            pk.x = *(uint32_t*)&h01;
            pk.y = *(uint32_t*)&h23;
            *(uint2*)(g_Ax + xbase) = pk;
            base  += stride;
            xbase += xstride;
        }
    } else {
#pragma unroll 4
        for (int s = 0; s < S_LEN; ++s) {
            const float4 z = ld_gates4(g_gates + base);
            const float4 f = ld_gates4(g_gates + base + H_DIM);
            c.x = fmaf(f.x, c.x - z.x, z.x);
            c.y = fmaf(f.y, c.y - z.y, z.y);
            c.z = fmaf(f.z, c.z - z.z, z.z);
            c.w = fmaf(f.w, c.w - z.w, z.w);
            base += stride;
        }
    }

    if (mode == 0) {
        *(float4*)(g_acc + flat) = c;
    } else if (mode == 1) {
        float4 a = *(const float4*)(g_acc + flat);
        a.x += c.x; a.y += c.y; a.z += c.z; a.w += c.w;
        *(float4*)(g_acc + flat) = a;
    } else {
        const float inv = 1.0f / (float)sent_len[b];
        float4 a = *(const float4*)(g_acc + flat);
        float4 v;
        v.x = (a.x + c.x) * inv;
        v.y = (a.y + c.y) * inv;
        v.z = (a.z + c.z) * inv;
        v.w = (a.w + c.w) * inv;
        *(float4*)(out + flat) = v;
    }
}

// ---------------------------------------------------------------------------
extern "C" void kernel_launch(void* const* d_in, const int* in_sizes, int n_in,
                              void* d_out, int out_size)
{
    const float* sent     = (const float*)d_in[0];
    const int*   sent_len = (const int*)  d_in[1];
    const float* W1 = (const float*)d_in[2];
    const float* b1 = (const float*)d_in[3];
    const float* W2 = (const float*)d_in[4];
    const float* b2 = (const float*)d_in[5];
    const float* W3 = (const float*)d_in[6];
    const float* b3 = (const float*)d_in[7];
    float* out = (float*)d_out;

    cudaFuncSetAttribute(gemm_tc, cudaFuncAttributeMaxDynamicSharedMemorySize, GEMM_SMEM_BYTES);

    cvt_W_kernel<<<N3H, 128>>>(W1, E_DIM / 4, K1PAD, 0);
    cvt_W_kernel<<<N3H, 128>>>(W2, H_DIM / 4, K2PAD, 1);
    cvt_W_kernel<<<N3H, 128>>>(W3, H_DIM / 4, K2PAD, 2);
    cvt_A1_kernel<<<M_ROWS, 64>>>(sent);

    const int nblocks = (M_ROWS / BM) * NGRP;             // 64 * 57 = 3648
    const int sblocks = ((B_SZ * H_DIM) / 4 + 127) / 128; // 150

    gemm_tc<<<nblocks, 256, GEMM_SMEM_BYTES>>>(1, b1);
    scan_kernel<<<sblocks, 128>>>(0, sent_len, out);

    gemm_tc<<<nblocks, 256, GEMM_SMEM_BYTES>>>(2, b2);
    scan_kernel<<<sblocks, 128>>>(1, sent_len, out);

    gemm_tc<<<nblocks, 256, GEMM_SMEM_BYTES>>>(3, b3);
    scan_kernel<<<sblocks, 128>>>(2, sent_len, out);
}